// round 7
// baseline (speedup 1.0000x reference)
#include <cuda_runtime.h>
#include <cuda_bf16.h>
#include <stdint.h>

#define BB 2
#define SS 1024
#define DD 512
#define HH 8
#define DKK 64
#define RR 16
#define GG 2
#define GDD 32
#define NHH 4
#define KMAX 64
#define NEGF (-1e30f)
#define TSLOTS 2048
#define MT 32            // m-tile rows for k_proj

typedef unsigned long long ull;

// ---------------- scratch (device globals; no allocation allowed) ----------
// g_htab empty marker is 0 (matches zero-init at module load); k_epi re-clears
// it at the end of every call so each replay starts empty.
__device__ float g_qup[BB*HH*SS*DKK];   // [b][h][s][k]
__device__ float g_kup[BB*HH*SS*DKK];
__device__ unsigned g_hq[BB*HH*GG*SS];  // packed 4 hash bytes
__device__ unsigned g_hk[BB*HH*GG*SS];
__device__ unsigned g_qsign[HH*GG*SS];  // q sign masks from batch B-1
__device__ ull g_htab[HH*GG][TSLOTS];   // (ksign<<32)|0x80000000|idx; 0=empty
__device__ int g_cand[BB*HH*SS*KMAX];
__device__ int g_ccount[BB*HH*SS];
// overflow buffers for the (astronomically rare) many-match fallback path
__device__ int   g_midx[(size_t)BB*HH*SS*1024];
__device__ float g_msc[(size_t)BB*HH*SS*1024];

__device__ __forceinline__ unsigned f2u_ord(float f) {
    unsigned u = __float_as_uint(f);
    return (u & 0x80000000u) ? ~u : (u | 0x80000000u);
}
__device__ __forceinline__ ull ffma2(ull a, ull b, ull c) {
    ull d;
    asm("fma.rn.f32x2 %0, %1, %2, %3;" : "=l"(d) : "l"(a), "l"(b), "l"(c));
    return d;
}
__device__ __forceinline__ ull packf2(float x, float y) {
    ull d;
    asm("mov.b64 %0, {%1, %2};" : "=l"(d) : "f"(x), "f"(y));
    return d;
}
__device__ __forceinline__ void unpackf2(ull v, float& lo, float& hi) {
    asm("mov.b64 {%0, %1}, %2;" : "=f"(lo), "=f"(hi) : "l"(v));
}

// ---------------- A: fused low-rank projection + hash/sign/insert -----------
// stage1: Ts[32 rows][64 cols] = X_tile @ A_tile (K=512)   (kept in smem)
// stage2: per covered head: out_tile[32x64] = Ts_h[32x16] @ B_h[16x64]
//         -> global + smem mirror Ot (scalar stores; stride 65 keeps stage3
//         column reads bank-conflict-free but is NOT float4-aligned)
// stage3: per head: hash + sign masks from Ot (smem), insert into htab
// grid (2048/32=64, 128/64=2, 2{q,k}), 256 thr  => 256 blocks
__global__ void __launch_bounds__(256, 4)
k_proj(const float* __restrict__ Xq, const float* __restrict__ Xk,
       const float* __restrict__ Aq, const float* __restrict__ Ak,
       const float* __restrict__ Bq, const float* __restrict__ Bk,
       const float* __restrict__ lsh) {
    int m0 = blockIdx.x * MT;
    int n0 = blockIdx.y * 64;
    int z = blockIdx.z;
    int tid = threadIdx.x;
    const float* X  = z ? Xk : Xq;
    const float* Am = z ? Ak : Aq;
    const float* Bm = z ? Bk : Bq;
    float* Out = z ? g_kup : g_qup;
    __shared__ float As[32][34];   // As[d][row]
    __shared__ float Bs[32][68];   // stage1 A-mat tile / stage2 B_h (16x64 used)
    __shared__ float Ts[32][68];   // stage1 result tile
    __shared__ float Ot[32][65];   // stage2 per-head out mirror (65 -> no conflicts)
    int tx = tid & 15, ty = tid >> 4;   // tx: col/4, ty: row-pair 0..15
    int b = m0 >> 10;
    int sbase = m0 & (SS - 1);
    int h0 = n0 >> 4;

    ull acc[4] = {};               // 2 rows (packed) x 4 cols
    for (int d0 = 0; d0 < DD; d0 += 32) {
        {   // load X tile 32 rows x 32 d, transposed into As[d][row]
            int r = tid >> 3, d4 = tid & 7;
            float4 v = *(const float4*)&X[(m0 + r) * DD + d0 + d4 * 4];
            As[d4*4+0][r] = v.x; As[d4*4+1][r] = v.y;
            As[d4*4+2][r] = v.z; As[d4*4+3][r] = v.w;
        }
#pragma unroll
        for (int t = 0; t < 2; t++) {   // load A-mat tile 32 d x 64 cols
            int lin = tid + t * 256;
            int r = lin >> 4;
            int cc = (lin & 15) * 4;
            int c = n0 + cc;
            int h = c >> 4, rr = c & 15;
            float4 v = *(const float4*)&Am[h * (DD * RR) + (d0 + r) * RR + rr];
            *(float4*)&Bs[r][cc] = v;
        }
        __syncthreads();
#pragma unroll
        for (int d = 0; d < 32; d++) {
            ull a01 = *(const ull*)&As[d][ty * 2];
            float4 bv = *(const float4*)&Bs[d][tx * 4];
            acc[0] = ffma2(a01, packf2(bv.x, bv.x), acc[0]);
            acc[1] = ffma2(a01, packf2(bv.y, bv.y), acc[1]);
            acc[2] = ffma2(a01, packf2(bv.z, bv.z), acc[2]);
            acc[3] = ffma2(a01, packf2(bv.w, bv.w), acc[3]);
        }
        __syncthreads();
    }
#pragma unroll
    for (int j = 0; j < 4; j++) {
        float lo, hi;
        unpackf2(acc[j], lo, hi);
        Ts[ty*2 + 0][tx*4 + j] = lo;
        Ts[ty*2 + 1][tx*4 + j] = hi;
    }
    __syncthreads();

    // stage2+3 per head
#pragma unroll
    for (int hl = 0; hl < 4; hl++) {
        int h = h0 + hl;
#pragma unroll
        for (int t = 0; t < 4; t++) {   // load B_h[16][64]
            int lin = tid + t * 256;
            int kk = lin >> 6, cc = lin & 63;
            Bs[kk][cc] = Bm[h * RR * DKK + kk * DKK + cc];
        }
        __syncthreads();
        float c4[2][4] = {};
#pragma unroll
        for (int kk = 0; kk < 16; kk++) {
            float a0 = Ts[ty*2+0][hl*16+kk];
            float a1 = Ts[ty*2+1][hl*16+kk];
            float4 bv = *(const float4*)&Bs[kk][tx * 4];
            c4[0][0] += a0*bv.x; c4[0][1] += a0*bv.y; c4[0][2] += a0*bv.z; c4[0][3] += a0*bv.w;
            c4[1][0] += a1*bv.x; c4[1][1] += a1*bv.y; c4[1][2] += a1*bv.z; c4[1][3] += a1*bv.w;
        }
#pragma unroll
        for (int i = 0; i < 2; i++) {
            int r = ty * 2 + i;
            float4 v = make_float4(c4[i][0], c4[i][1], c4[i][2], c4[i][3]);
            *(float4*)&Out[(((b * HH + h) * SS) + sbase + r) * DKK + tx * 4] = v;
            // scalar mirror stores (stride-65 rows are not 16B-aligned)
            Ot[r][tx*4 + 0] = v.x;
            Ot[r][tx*4 + 1] = v.y;
            Ot[r][tx*4 + 2] = v.z;
            Ot[r][tx*4 + 3] = v.w;
        }
        __syncthreads();
        // stage3 for this head: 64 items = 2 groups x 32 rows (tid < 64)
        if (tid < 64) {
            int g = tid >> 5, r = tid & 31;
            int s = sbase + r;
            const float4* pr = (const float4*)&lsh[(h * GG + g) * GDD * NHH];
            float a0 = 0.f, a1 = 0.f, a2 = 0.f, a3 = 0.f;
            unsigned sg = 0u;
#pragma unroll
            for (int d = 0; d < GDD; d++) {
                float v = Ot[r][g * GDD + d];
                float4 p = pr[d];
                if (v > 0.f) sg |= (1u << d);
                a0 += v * p.x; a1 += v * p.y; a2 += v * p.z; a3 += v * p.w;
            }
            unsigned hw = ((unsigned)(((int)floorf(a0 * 0.25f)) & 63))
                        | ((unsigned)(((int)floorf(a1 * 0.25f)) & 63) << 8)
                        | ((unsigned)(((int)floorf(a2 * 0.25f)) & 63) << 16)
                        | ((unsigned)(((int)floorf(a3 * 0.25f)) & 63) << 24);
            int idx = ((b * HH + h) * GG + g) * SS + s;
            if (z == 0) {
                g_hq[idx] = hw;
                if (b == BB - 1) g_qsign[(h * GG + g) * SS + s] = sg;
            } else {
                g_hk[idx] = hw;
                if (b == BB - 1) {
                    ull entry = (((ull)sg) << 32) | 0x80000000u | (unsigned)s;
                    unsigned slot = (sg * 2654435761u) >> 21;
                    while (atomicCAS(&g_htab[h * GG + g][slot & (TSLOTS - 1)], 0ull, entry) != 0ull)
                        slot++;
                }
            }
        }
    }
}

// ---------------- B: candidate generation (warp per row, lazy) --------------
__global__ void k_cand() {
    __shared__ unsigned unionw[4][32];
    __shared__ unsigned gmask[4][32];
    __shared__ int shcnt[4];
    int tid = threadIdx.x, wid = tid >> 5, lane = tid & 31;
    int row = blockIdx.x * 4 + wid;
    int s = row & (SS - 1), h = (row >> 10) & 7, b = row >> 13;
    unionw[wid][lane] = 0u;
    __syncwarp();
    for (int g = 0; g < GG; g++) {
        gmask[wid][lane] = 0u;
        __syncwarp();
        int hg = h * GG + g;
        unsigned qsig = g_qsign[hg * SS + s];
        unsigned hqv = g_hq[((b * HH + h) * GG + g) * SS + s];
        const ull* tab = g_htab[hg];
        const unsigned* hkp = &g_hk[((b * HH + h) * GG + g) * SS];
        unsigned start = (qsig * 2654435761u) >> 21;
        int gcnt = 0;
        for (int w = 0; w < TSLOTS / 32; w++) {
            int p = (start + w * 32 + lane) & (TSLOTS - 1);
            ull e = tab[p];
            bool empty = (e == 0ull);
            unsigned em = __ballot_sync(0xffffffffu, empty);
            unsigned valid = em ? ((em & (unsigned)(-(int)em)) - 1u) : 0xffffffffu;
            bool mt = false; int j = 0;
            if (!empty && ((valid >> lane) & 1u) && (unsigned)(e >> 32) == qsig) {
                j = (int)(e & 0x3FFu);
                mt = (__vcmpeq4(hqv, hkp[j]) != 0u);
            }
            unsigned bal = __ballot_sync(0xffffffffu, mt);
            if (mt) atomicOr(&gmask[wid][j >> 5], 1u << (j & 31));
            gcnt += __popc(bal);
            if (em) break;
        }
        if (gcnt > KMAX) {
            // rare fallback: compute scores for flagged j's, exact 64th-largest
            const float* qbase = &g_qup[row * DKK + g * GDD];
            const float* kbase = &g_kup[(b * HH + h) * SS * DKK + g * GDD];
            int* mix = &g_midx[(size_t)row * 1024];
            float* msf = &g_msc[(size_t)row * 1024];
            if (lane == 0) shcnt[wid] = 0;
            __syncwarp();
            unsigned w = gmask[wid][lane];
            while (w) {
                int bpos = __ffs(w) - 1;
                w &= w - 1;
                int j = lane * 32 + bpos;
                float a = 0.f;
                const float* kr = kbase + j * DKK;
#pragma unroll
                for (int d = 0; d < GDD; d++) a += qbase[d] * kr[d];
                int rk = atomicAdd(&shcnt[wid], 1);
                mix[rk] = j; msf[rk] = a;
            }
            __syncwarp();
            gmask[wid][lane] = 0u;
            __syncwarp();
            unsigned prefix = 0u; int kk = KMAX;
            for (int bit = 31; bit >= 0; bit--) {
                int local = 0;
                for (int i = lane; i < gcnt; i += 32) {
                    unsigned key = f2u_ord(msf[i]);
                    unsigned hi2 = (bit == 31) ? 0u : (key >> (bit + 1));
                    if (hi2 == prefix && ((key >> bit) & 1u)) local++;
                }
#pragma unroll
                for (int off = 16; off; off >>= 1) local += __shfl_xor_sync(0xffffffffu, local, off);
                if (local >= kk) prefix = (prefix << 1) | 1u;
                else { kk -= local; prefix <<= 1; }
            }
            for (int i = lane; i < gcnt; i += 32)
                if (f2u_ord(msf[i]) >= prefix)
                    atomicOr(&gmask[wid][mix[i] >> 5], 1u << (mix[i] & 31));
        }
        __syncwarp();
        unionw[wid][lane] |= gmask[wid][lane];
        __syncwarp();
    }
    unsigned w = unionw[wid][lane];
    int c = __popc(w);
    int pre = c;
#pragma unroll
    for (int off = 1; off < 32; off <<= 1) {
        int n = __shfl_up_sync(0xffffffffu, pre, off);
        if (lane >= off) pre += n;
    }
    int excl = pre - c;
    int total = __shfl_sync(0xffffffffu, pre, 31);
    if (lane == 0) g_ccount[row] = (total > KMAX) ? KMAX : total;
    if (total > 0) {
        int* crow = &g_cand[row * KMAX];
        int rank = excl;
        while (w && rank < KMAX) {
            int bpos = __ffs(w) - 1;
            w &= w - 1;
            crow[rank++] = lane * 32 + bpos;
        }
    }
}

// ---------------- C: epilogue (zero-fill fast path; full fallback) -----------
// grid (S/64, DD/64, B), 256 thr. Per block: check its 512 row counts;
// all-zero -> zero out tile. Else compute attn (vup on the fly) + out proj.
// Also clears g_htab for the next call.
__global__ void k_epi(const float* __restrict__ value, const float* __restrict__ Wv,
                      const float* __restrict__ Wo, float* __restrict__ out) {
    int stile = blockIdx.x, ntile = blockIdx.y, b = blockIdx.z;
    int sbase = stile * 64, n0 = ntile * 64;
    int tid = threadIdx.x;
    __shared__ int nzflag;
    if (tid == 0) nzflag = 0;
    __syncthreads();
    int any = 0;
#pragma unroll
    for (int t = 0; t < 2; t++) {
        int item = tid + t * 256;       // 512 = 8 heads x 64 rows
        int h = item >> 6, r = item & 63;
        if (g_ccount[(b * HH + h) * SS + sbase + r] > 0) any = 1;
    }
    if (any) atomicOr(&nzflag, 1);
    // clear htab for next call (nothing reads it after k_cand)
    {
        int lin = ((b * gridDim.y + ntile) * gridDim.x + stile) * 256 + tid;
        if (lin < HH * GG * TSLOTS) ((ull*)g_htab)[lin] = 0ull;
    }
    __syncthreads();
    if (!nzflag) {
        float4 z4 = make_float4(0.f, 0.f, 0.f, 0.f);
#pragma unroll
        for (int t = 0; t < 4; t++) {
            int lin = tid + t * 256;    // 1024 float4 = 64 rows x 16
            int r = lin >> 4, c4i = lin & 15;
            *(float4*)&out[(b * SS + sbase + r) * DD + n0 + c4i * 4] = z4;
        }
        return;
    }
    // ---------- fallback: full sparse attention + output projection ----------
    __shared__ float Oh[64][65];
    __shared__ float Ws[64][65];
    __shared__ float sl[8][KMAX];
    int lane = tid & 31, w = tid >> 5;
    int tx = tid & 15, ty = tid >> 4;
    float acc[4][4] = {};
    for (int h = 0; h < HH; h++) {
        for (int rr = 0; rr < 8; rr++) {
            int r = w * 8 + rr;
            int row = (b * HH + h) * SS + sbase + r;
            int cnt = g_ccount[row];
            float o0 = 0.f, o1 = 0.f;
            if (cnt > 0) {
                const int* crow = &g_cand[row * KMAX];
                const float* q = &g_qup[row * DKK];
                const float* kb2 = &g_kup[(b * HH + h) * SS * DKK];
                float mx = NEGF;
                for (int c = 0; c < cnt; c++) {
                    int j = crow[c];
                    const float* kr = kb2 + j * DKK;
                    float a = q[lane] * kr[lane] + q[lane + 32] * kr[lane + 32];
#pragma unroll
                    for (int off = 16; off; off >>= 1) a += __shfl_xor_sync(0xffffffffu, a, off);
                    a *= 0.125f;
                    if (lane == 0) sl[w][c] = a;
                    mx = fmaxf(mx, a);
                }
                __syncwarp();
                float sum = 0.f;
                for (int c = 0; c < cnt; c++) {
                    float e = expf(sl[w][c] - mx);
                    sum += e;
                }
                __syncwarp();
                float inv = (sum > 0.f) ? (1.f / sum) : 0.f;
                for (int c = 0; c < cnt; c++) {
                    int j = crow[c];
                    float p = expf(sl[w][c] - mx) * inv;
                    const float* vr = &value[(b * SS + j) * DD];
                    const float* wv = &Wv[h * DD * DKK];
                    float v0 = 0.f, v1 = 0.f;
                    for (int d = 0; d < DD; d++) {
                        float vv = vr[d];
                        v0 += vv * wv[d * DKK + lane];
                        v1 += vv * wv[d * DKK + lane + 32];
                    }
                    o0 += p * v0; o1 += p * v1;
                }
            }
            Oh[r][lane] = o0; Oh[r][lane + 32] = o1;
        }
        __syncthreads();
#pragma unroll
        for (int t = 0; t < 16; t++) {
            int lin = tid + t * 256;    // 4096 = 64x64
            int kk = lin >> 6, cc = lin & 63;
            Ws[kk][cc] = Wo[(h * DKK + kk) * DD + n0 + cc];
        }
        __syncthreads();
        for (int kk = 0; kk < DKK; kk++) {
            float a0 = Oh[ty*4+0][kk], a1 = Oh[ty*4+1][kk];
            float a2 = Oh[ty*4+2][kk], a3 = Oh[ty*4+3][kk];
            float b0 = Ws[kk][tx*4+0], b1 = Ws[kk][tx*4+1];
            float b2 = Ws[kk][tx*4+2], b3 = Ws[kk][tx*4+3];
            acc[0][0] += a0*b0; acc[0][1] += a0*b1; acc[0][2] += a0*b2; acc[0][3] += a0*b3;
            acc[1][0] += a1*b0; acc[1][1] += a1*b1; acc[1][2] += a1*b2; acc[1][3] += a1*b3;
            acc[2][0] += a2*b0; acc[2][1] += a2*b1; acc[2][2] += a2*b2; acc[2][3] += a2*b3;
            acc[3][0] += a3*b0; acc[3][1] += a3*b1; acc[3][2] += a3*b2; acc[3][3] += a3*b3;
        }
        __syncthreads();
    }
#pragma unroll
    for (int i = 0; i < 4; i++) {
        float4 v = make_float4(acc[i][0], acc[i][1], acc[i][2], acc[i][3]);
        *(float4*)&out[(b * SS + sbase + ty * 4 + i) * DD + n0 + tx * 4] = v;
    }
}

// ---------------- launch ----------------------------------------------------
extern "C" void kernel_launch(void* const* d_in, const int* in_sizes, int n_in,
                              void* d_out, int out_size) {
    const float* query = (const float*)d_in[0];
    const float* key   = (const float*)d_in[1];
    const float* value = (const float*)d_in[2];
    const float* Aq    = (const float*)d_in[3];
    const float* Bq    = (const float*)d_in[4];
    const float* Ak    = (const float*)d_in[5];
    const float* Bk    = (const float*)d_in[6];
    const float* Wv    = (const float*)d_in[7];
    const float* Wo    = (const float*)d_in[8];
    const float* lsh   = (const float*)d_in[9];
    float* out = (float*)d_out;

    k_proj<<<dim3(BB * SS / MT, (HH * RR) / 64, 2), 256>>>(query, key, Aq, Ak, Bq, Bk, lsh);
    k_cand<<<BB * HH * SS / 4, 128>>>();
    k_epi<<<dim3(SS / 64, DD / 64, BB), 256>>>(value, Wv, Wo, out);
}

// round 9
// speedup vs baseline: 1.0013x; 1.0013x over previous
#include <cuda_runtime.h>
#include <cuda_bf16.h>
#include <stdint.h>

#define BB 2
#define SS 1024
#define DD 512
#define HH 8
#define DKK 64
#define RR 16
#define GG 2
#define GDD 32
#define NHH 4
#define KMAX 64
#define NEGF (-1e30f)
#define TSLOTS 2048

typedef unsigned long long ull;

// ---------------- scratch (device globals; no allocation allowed) ----------
// g_htab empty marker is 0 (matches zero-init at module load); k_epi re-clears
// it at the end of every call so each replay starts empty.
__device__ float g_qup[BB*HH*SS*DKK];   // [b][h][s][k]
__device__ float g_kup[BB*HH*SS*DKK];
__device__ unsigned g_hq[BB*HH*GG*SS];  // packed 4 hash bytes
__device__ unsigned g_hk[BB*HH*GG*SS];
__device__ unsigned g_qsign[HH*GG*SS];  // q sign masks from batch B-1
__device__ ull g_htab[HH*GG][TSLOTS];   // (ksign<<32)|0x80000000|idx; 0=empty
__device__ int g_cand[BB*HH*SS*KMAX];
__device__ int g_ccount[BB*HH*SS];
// overflow buffers for the (astronomically rare) many-match fallback path
__device__ int   g_midx[(size_t)BB*HH*SS*1024];
__device__ float g_msc[(size_t)BB*HH*SS*1024];

__device__ __forceinline__ unsigned f2u_ord(float f) {
    unsigned u = __float_as_uint(f);
    return (u & 0x80000000u) ? ~u : (u | 0x80000000u);
}
__device__ __forceinline__ ull ffma2(ull a, ull b, ull c) {
    ull d;
    asm("fma.rn.f32x2 %0, %1, %2, %3;" : "=l"(d) : "l"(a), "l"(b), "l"(c));
    return d;
}
__device__ __forceinline__ void unpackf2(ull v, float& lo, float& hi) {
    asm("mov.b64 {%0, %1}, %2;" : "=f"(lo), "=f"(hi) : "l"(v));
}

// ---------------- A: fused low-rank projection + hash/sign/insert -----------
// stage1: Ts[64][64] = X_tile[64x512] @ A_tile[512x64], K-chunks of 32.
//   smem: As2f[d][row] (X transposed; consumed as row-pair f32x2) and
//         Bdupf[d][2c..2c+1] (projection value duplicated -> native f32x2
//         broadcast operand, zero MOVs).
//   warp shape: 8 row-threads x 4 col-threads; microtile 4x4 per thread.
// stage2: per covered head: out[64x64] = Ts_h[64x16] @ B_h[16x64]
// stage3: per head: hash + sign masks from smem mirror, insert into htab
// grid (2048/64=32, 128/64=2, 2{q,k}) = 128 blocks, 256 thr
__global__ void __launch_bounds__(256)
k_proj(const float* __restrict__ Xq, const float* __restrict__ Xk,
       const float* __restrict__ Aq, const float* __restrict__ Ak,
       const float* __restrict__ Bq, const float* __restrict__ Bk,
       const float* __restrict__ lsh) {
    int m0 = blockIdx.x * 64;
    int n0 = blockIdx.y * 64;
    int z = blockIdx.z;
    int tid = threadIdx.x;
    const float* X  = z ? Xk : Xq;
    const float* Am = z ? Ak : Aq;
    const float* Bm = z ? Bk : Bq;
    float* Out = z ? g_kup : g_qup;

    __shared__ __align__(16) float As2f[32][68];    // ull view stride 34
    __shared__ __align__(16) float Bdupf[32][136];  // ull view stride 68
    __shared__ __align__(16) float Ts[64][68];

    int w = tid >> 5, l = tid & 31;
    int lr = l & 7, lc = l >> 3;
    int rbase = (w & 1) * 32 + lr * 4;      // 4 rows
    int cbase = (w >> 1) * 16 + lc * 4;     // 4 cols
    int b = m0 >> 10;
    int sbase = m0 & (SS - 1);
    int h0 = n0 >> 4;

    const ull* As2u = (const ull*)&As2f[0][0];   // [d][rp], stride 34
    const ull* Bdu  = (const ull*)&Bdupf[0][0];  // [d][c dup], stride 68
    int rp0 = rbase >> 1;

    ull acc[2][4] = {};          // 2 row-pairs x 4 cols
    for (int d0 = 0; d0 < DD; d0 += 32) {
        // load X tile 64 rows x 32 d, transposed
#pragma unroll
        for (int t = 0; t < 2; t++) {
            int lin = tid + t * 256;
            int row = lin >> 3, dq = lin & 7;
            float4 v = *(const float4*)&X[(m0 + row) * DD + d0 + dq * 4];
            As2f[dq*4+0][row] = v.x; As2f[dq*4+1][row] = v.y;
            As2f[dq*4+2][row] = v.z; As2f[dq*4+3][row] = v.w;
        }
        // load A-proj tile 32 d x 64 cols, duplicated
#pragma unroll
        for (int t = 0; t < 8; t++) {
            int lin = tid + t * 256;
            int r = lin >> 6, c = lin & 63;
            int gc = n0 + c;
            int h = gc >> 4, rr = gc & 15;
            float bv = Am[h * (DD * RR) + (d0 + r) * RR + rr];
            Bdupf[r][2*c]   = bv;
            Bdupf[r][2*c+1] = bv;
        }
        __syncthreads();
#pragma unroll
        for (int d = 0; d < 32; d++) {
            ulonglong2 av  = *(const ulonglong2*)&As2u[d * 34 + rp0];
            ulonglong2 b01 = *(const ulonglong2*)&Bdu[d * 68 + cbase];
            ulonglong2 b23 = *(const ulonglong2*)&Bdu[d * 68 + cbase + 2];
            acc[0][0] = ffma2(av.x, b01.x, acc[0][0]);
            acc[0][1] = ffma2(av.x, b01.y, acc[0][1]);
            acc[0][2] = ffma2(av.x, b23.x, acc[0][2]);
            acc[0][3] = ffma2(av.x, b23.y, acc[0][3]);
            acc[1][0] = ffma2(av.y, b01.x, acc[1][0]);
            acc[1][1] = ffma2(av.y, b01.y, acc[1][1]);
            acc[1][2] = ffma2(av.y, b23.x, acc[1][2]);
            acc[1][3] = ffma2(av.y, b23.y, acc[1][3]);
        }
        __syncthreads();
    }
    // stage1 result -> Ts
#pragma unroll
    for (int p = 0; p < 2; p++)
#pragma unroll
        for (int j = 0; j < 4; j++) {
            float lo, hi;
            unpackf2(acc[p][j], lo, hi);
            Ts[rbase + 2*p + 0][cbase + j] = lo;
            Ts[rbase + 2*p + 1][cbase + j] = hi;
        }
    __syncthreads();

    // stage2+3 per head; overlay smem: Bs on As2f, Ot on Bdupf
    float (*Bs)[68] = (float(*)[68])&As2f[0][0];      // 16x68 used
    float (*Ot)[65] = (float(*)[65])&Bdupf[0][0];     // 64x65 used (17408B >= 16640B)
    int tx = tid & 15, ty = tid >> 4;
#pragma unroll
    for (int hl = 0; hl < 4; hl++) {
        int h = h0 + hl;
#pragma unroll
        for (int t = 0; t < 4; t++) {   // B_h[16][64]
            int lin = tid + t * 256;
            int kk = lin >> 6, cc = lin & 63;
            Bs[kk][cc] = Bm[h * RR * DKK + kk * DKK + cc];
        }
        __syncthreads();
        float c4[4][4] = {};
#pragma unroll
        for (int kk = 0; kk < 16; kk++) {
            float a0 = Ts[ty*4+0][hl*16+kk], a1 = Ts[ty*4+1][hl*16+kk];
            float a2 = Ts[ty*4+2][hl*16+kk], a3 = Ts[ty*4+3][hl*16+kk];
            float4 bv = *(const float4*)&Bs[kk][tx * 4];
            c4[0][0] += a0*bv.x; c4[0][1] += a0*bv.y; c4[0][2] += a0*bv.z; c4[0][3] += a0*bv.w;
            c4[1][0] += a1*bv.x; c4[1][1] += a1*bv.y; c4[1][2] += a1*bv.z; c4[1][3] += a1*bv.w;
            c4[2][0] += a2*bv.x; c4[2][1] += a2*bv.y; c4[2][2] += a2*bv.z; c4[2][3] += a2*bv.w;
            c4[3][0] += a3*bv.x; c4[3][1] += a3*bv.y; c4[3][2] += a3*bv.z; c4[3][3] += a3*bv.w;
        }
#pragma unroll
        for (int i = 0; i < 4; i++) {
            int r = ty * 4 + i;
            float4 v = make_float4(c4[i][0], c4[i][1], c4[i][2], c4[i][3]);
            *(float4*)&Out[(((b * HH + h) * SS) + sbase + r) * DKK + tx * 4] = v;
            Ot[r][tx*4 + 0] = v.x;   // stride-65 rows: scalar stores
            Ot[r][tx*4 + 1] = v.y;
            Ot[r][tx*4 + 2] = v.z;
            Ot[r][tx*4 + 3] = v.w;
        }
        __syncthreads();
        // stage3: 128 items = 2 groups x 64 rows
        if (tid < 128) {
            int g = tid >> 6, r = tid & 63;
            int s = sbase + r;
            const float4* pr = (const float4*)&lsh[(h * GG + g) * GDD * NHH];
            float a0 = 0.f, a1 = 0.f, a2 = 0.f, a3 = 0.f;
            unsigned sg = 0u;
#pragma unroll
            for (int d = 0; d < GDD; d++) {
                float v = Ot[r][g * GDD + d];
                float4 p = pr[d];
                if (v > 0.f) sg |= (1u << d);
                a0 += v * p.x; a1 += v * p.y; a2 += v * p.z; a3 += v * p.w;
            }
            unsigned hw = ((unsigned)(((int)floorf(a0 * 0.25f)) & 63))
                        | ((unsigned)(((int)floorf(a1 * 0.25f)) & 63) << 8)
                        | ((unsigned)(((int)floorf(a2 * 0.25f)) & 63) << 16)
                        | ((unsigned)(((int)floorf(a3 * 0.25f)) & 63) << 24);
            int idx = ((b * HH + h) * GG + g) * SS + s;
            if (z == 0) {
                g_hq[idx] = hw;
                if (b == BB - 1) g_qsign[(h * GG + g) * SS + s] = sg;
            } else {
                g_hk[idx] = hw;
                if (b == BB - 1) {
                    ull entry = (((ull)sg) << 32) | 0x80000000u | (unsigned)s;
                    unsigned slot = (sg * 2654435761u) >> 21;
                    while (atomicCAS(&g_htab[h * GG + g][slot & (TSLOTS - 1)], 0ull, entry) != 0ull)
                        slot++;
                }
            }
        }
        __syncthreads();
    }
}

// ---------------- B: candidate generation (warp per row, lazy) --------------
__global__ void k_cand() {
    __shared__ unsigned unionw[4][32];
    __shared__ unsigned gmask[4][32];
    __shared__ int shcnt[4];
    int tid = threadIdx.x, wid = tid >> 5, lane = tid & 31;
    int row = blockIdx.x * 4 + wid;
    int s = row & (SS - 1), h = (row >> 10) & 7, b = row >> 13;
    unionw[wid][lane] = 0u;
    __syncwarp();
    for (int g = 0; g < GG; g++) {
        gmask[wid][lane] = 0u;
        __syncwarp();
        int hg = h * GG + g;
        unsigned qsig = g_qsign[hg * SS + s];
        unsigned hqv = g_hq[((b * HH + h) * GG + g) * SS + s];
        const ull* tab = g_htab[hg];
        const unsigned* hkp = &g_hk[((b * HH + h) * GG + g) * SS];
        unsigned start = (qsig * 2654435761u) >> 21;
        int gcnt = 0;
        for (int w = 0; w < TSLOTS / 32; w++) {
            int p = (start + w * 32 + lane) & (TSLOTS - 1);
            ull e = tab[p];
            bool empty = (e == 0ull);
            unsigned em = __ballot_sync(0xffffffffu, empty);
            unsigned valid = em ? ((em & (unsigned)(-(int)em)) - 1u) : 0xffffffffu;
            bool mt = false; int j = 0;
            if (!empty && ((valid >> lane) & 1u) && (unsigned)(e >> 32) == qsig) {
                j = (int)(e & 0x3FFu);
                mt = (__vcmpeq4(hqv, hkp[j]) != 0u);
            }
            unsigned bal = __ballot_sync(0xffffffffu, mt);
            if (mt) atomicOr(&gmask[wid][j >> 5], 1u << (j & 31));
            gcnt += __popc(bal);
            if (em) break;
        }
        if (gcnt > KMAX) {
            // rare fallback: compute scores for flagged j's, exact 64th-largest
            const float* qbase = &g_qup[row * DKK + g * GDD];
            const float* kbase = &g_kup[(b * HH + h) * SS * DKK + g * GDD];
            int* mix = &g_midx[(size_t)row * 1024];
            float* msf = &g_msc[(size_t)row * 1024];
            if (lane == 0) shcnt[wid] = 0;
            __syncwarp();
            unsigned w = gmask[wid][lane];
            while (w) {
                int bpos = __ffs(w) - 1;
                w &= w - 1;
                int j = lane * 32 + bpos;
                float a = 0.f;
                const float* kr = kbase + j * DKK;
#pragma unroll
                for (int d = 0; d < GDD; d++) a += qbase[d] * kr[d];
                int rk = atomicAdd(&shcnt[wid], 1);
                mix[rk] = j; msf[rk] = a;
            }
            __syncwarp();
            gmask[wid][lane] = 0u;
            __syncwarp();
            unsigned prefix = 0u; int kk = KMAX;
            for (int bit = 31; bit >= 0; bit--) {
                int local = 0;
                for (int i = lane; i < gcnt; i += 32) {
                    unsigned key = f2u_ord(msf[i]);
                    unsigned hi2 = (bit == 31) ? 0u : (key >> (bit + 1));
                    if (hi2 == prefix && ((key >> bit) & 1u)) local++;
                }
#pragma unroll
                for (int off = 16; off; off >>= 1) local += __shfl_xor_sync(0xffffffffu, local, off);
                if (local >= kk) prefix = (prefix << 1) | 1u;
                else { kk -= local; prefix <<= 1; }
            }
            for (int i = lane; i < gcnt; i += 32)
                if (f2u_ord(msf[i]) >= prefix)
                    atomicOr(&gmask[wid][mix[i] >> 5], 1u << (mix[i] & 31));
        }
        __syncwarp();
        unionw[wid][lane] |= gmask[wid][lane];
        __syncwarp();
    }
    unsigned w = unionw[wid][lane];
    int c = __popc(w);
    int pre = c;
#pragma unroll
    for (int off = 1; off < 32; off <<= 1) {
        int n = __shfl_up_sync(0xffffffffu, pre, off);
        if (lane >= off) pre += n;
    }
    int excl = pre - c;
    int total = __shfl_sync(0xffffffffu, pre, 31);
    if (lane == 0) g_ccount[row] = (total > KMAX) ? KMAX : total;
    if (total > 0) {
        int* crow = &g_cand[row * KMAX];
        int rank = excl;
        while (w && rank < KMAX) {
            int bpos = __ffs(w) - 1;
            w &= w - 1;
            crow[rank++] = lane * 32 + bpos;
        }
    }
}

// ---------------- C: epilogue (zero-fill fast path; full fallback) -----------
// grid (S/64, DD/64, B), 256 thr. Per block: check its 512 row counts;
// all-zero -> zero out tile. Else compute attn (vup on the fly) + out proj.
// Also clears g_htab for the next call.
__global__ void k_epi(const float* __restrict__ value, const float* __restrict__ Wv,
                      const float* __restrict__ Wo, float* __restrict__ out) {
    int stile = blockIdx.x, ntile = blockIdx.y, b = blockIdx.z;
    int sbase = stile * 64, n0 = ntile * 64;
    int tid = threadIdx.x;
    __shared__ int nzflag;
    if (tid == 0) nzflag = 0;
    __syncthreads();
    int any = 0;
#pragma unroll
    for (int t = 0; t < 2; t++) {
        int item = tid + t * 256;       // 512 = 8 heads x 64 rows
        int h = item >> 6, r = item & 63;
        if (g_ccount[(b * HH + h) * SS + sbase + r] > 0) any = 1;
    }
    if (any) atomicOr(&nzflag, 1);
    // clear htab for next call (nothing reads it after k_cand)
    {
        int lin = ((b * gridDim.y + ntile) * gridDim.x + stile) * 256 + tid;
        if (lin < HH * GG * TSLOTS) ((ull*)g_htab)[lin] = 0ull;
    }
    __syncthreads();
    if (!nzflag) {
        float4 z4 = make_float4(0.f, 0.f, 0.f, 0.f);
#pragma unroll
        for (int t = 0; t < 4; t++) {
            int lin = tid + t * 256;    // 1024 float4 = 64 rows x 16
            int r = lin >> 4, c4i = lin & 15;
            *(float4*)&out[(b * SS + sbase + r) * DD + n0 + c4i * 4] = z4;
        }
        return;
    }
    // ---------- fallback: full sparse attention + output projection ----------
    __shared__ float Oh[64][65];
    __shared__ float Ws[64][65];
    __shared__ float sl[8][KMAX];
    int lane = tid & 31, w = tid >> 5;
    int tx = tid & 15, ty = tid >> 4;
    float acc[4][4] = {};
    for (int h = 0; h < HH; h++) {
        for (int rr = 0; rr < 8; rr++) {
            int r = w * 8 + rr;
            int row = (b * HH + h) * SS + sbase + r;
            int cnt = g_ccount[row];
            float o0 = 0.f, o1 = 0.f;
            if (cnt > 0) {
                const int* crow = &g_cand[row * KMAX];
                const float* q = &g_qup[row * DKK];
                const float* kb2 = &g_kup[(b * HH + h) * SS * DKK];
                float mx = NEGF;
                for (int c = 0; c < cnt; c++) {
                    int j = crow[c];
                    const float* kr = kb2 + j * DKK;
                    float a = q[lane] * kr[lane] + q[lane + 32] * kr[lane + 32];
#pragma unroll
                    for (int off = 16; off; off >>= 1) a += __shfl_xor_sync(0xffffffffu, a, off);
                    a *= 0.125f;
                    if (lane == 0) sl[w][c] = a;
                    mx = fmaxf(mx, a);
                }
                __syncwarp();
                float sum = 0.f;
                for (int c = 0; c < cnt; c++) {
                    float e = expf(sl[w][c] - mx);
                    sum += e;
                }
                __syncwarp();
                float inv = (sum > 0.f) ? (1.f / sum) : 0.f;
                for (int c = 0; c < cnt; c++) {
                    int j = crow[c];
                    float p = expf(sl[w][c] - mx) * inv;
                    const float* vr = &value[(b * SS + j) * DD];
                    const float* wv = &Wv[h * DD * DKK];
                    float v0 = 0.f, v1 = 0.f;
                    for (int d = 0; d < DD; d++) {
                        float vv = vr[d];
                        v0 += vv * wv[d * DKK + lane];
                        v1 += vv * wv[d * DKK + lane + 32];
                    }
                    o0 += p * v0; o1 += p * v1;
                }
            }
            Oh[r][lane] = o0; Oh[r][lane + 32] = o1;
        }
        __syncthreads();
#pragma unroll
        for (int t = 0; t < 16; t++) {
            int lin = tid + t * 256;    // 4096 = 64x64
            int kk = lin >> 6, cc = lin & 63;
            Ws[kk][cc] = Wo[(h * DKK + kk) * DD + n0 + cc];
        }
        __syncthreads();
        for (int kk = 0; kk < DKK; kk++) {
            float a0 = Oh[ty*4+0][kk], a1 = Oh[ty*4+1][kk];
            float a2 = Oh[ty*4+2][kk], a3 = Oh[ty*4+3][kk];
            float b0 = Ws[kk][tx*4+0], b1 = Ws[kk][tx*4+1];
            float b2 = Ws[kk][tx*4+2], b3 = Ws[kk][tx*4+3];
            acc[0][0] += a0*b0; acc[0][1] += a0*b1; acc[0][2] += a0*b2; acc[0][3] += a0*b3;
            acc[1][0] += a1*b0; acc[1][1] += a1*b1; acc[1][2] += a1*b2; acc[1][3] += a1*b3;
            acc[2][0] += a2*b0; acc[2][1] += a2*b1; acc[2][2] += a2*b2; acc[2][3] += a2*b3;
            acc[3][0] += a3*b0; acc[3][1] += a3*b1; acc[3][2] += a3*b2; acc[3][3] += a3*b3;
        }
        __syncthreads();
    }
#pragma unroll
    for (int i = 0; i < 4; i++) {
        float4 v = make_float4(acc[i][0], acc[i][1], acc[i][2], acc[i][3]);
        *(float4*)&out[(b * SS + sbase + ty * 4 + i) * DD + n0 + tx * 4] = v;
    }
}

// ---------------- launch ----------------------------------------------------
extern "C" void kernel_launch(void* const* d_in, const int* in_sizes, int n_in,
                              void* d_out, int out_size) {
    const float* query = (const float*)d_in[0];
    const float* key   = (const float*)d_in[1];
    const float* value = (const float*)d_in[2];
    const float* Aq    = (const float*)d_in[3];
    const float* Bq    = (const float*)d_in[4];
    const float* Ak    = (const float*)d_in[5];
    const float* Bk    = (const float*)d_in[6];
    const float* Wv    = (const float*)d_in[7];
    const float* Wo    = (const float*)d_in[8];
    const float* lsh   = (const float*)d_in[9];
    float* out = (float*)d_out;

    k_proj<<<dim3(BB * SS / 64, (HH * RR) / 64, 2), 256>>>(query, key, Aq, Ak, Bq, Bk, lsh);
    k_cand<<<BB * HH * SS / 4, 128>>>();
    k_epi<<<dim3(SS / 64, DD / 64, BB), 256>>>(value, Wv, Wo, out);
}

// round 11
// speedup vs baseline: 1.0308x; 1.0294x over previous
#include <cuda_runtime.h>
#include <cuda_bf16.h>
#include <stdint.h>

#define BB 2
#define SS 1024
#define DD 512
#define HH 8
#define DKK 64
#define RR 16
#define GG 2
#define GDD 32
#define NHH 4
#define KMAX 64
#define NEGF (-1e30f)
#define TSLOTS 2048

typedef unsigned long long ull;

// ---------------- scratch (device globals; no allocation allowed) ----------
// g_htab empty marker is 0 (matches zero-init at module load); k_epi re-clears
// it at the end of every call so each replay starts empty.
__device__ float g_qup[BB*HH*SS*DKK];   // [b][h][s][k]
__device__ float g_kup[BB*HH*SS*DKK];
__device__ unsigned g_hq[BB*HH*GG*SS];  // packed 4 hash bytes
__device__ unsigned g_hk[BB*HH*GG*SS];
__device__ unsigned g_qsign[HH*GG*SS];  // q sign masks from batch B-1
__device__ ull g_htab[HH*GG][TSLOTS];   // (ksign<<32)|0x80000000|idx; 0=empty
__device__ int g_cand[BB*HH*SS*KMAX];
__device__ int g_ccount[BB*HH*SS];
// overflow buffers for the (astronomically rare) many-match fallback path
__device__ int   g_midx[(size_t)BB*HH*SS*1024];
__device__ float g_msc[(size_t)BB*HH*SS*1024];

__device__ __forceinline__ unsigned f2u_ord(float f) {
    unsigned u = __float_as_uint(f);
    return (u & 0x80000000u) ? ~u : (u | 0x80000000u);
}

// ---------------- A: fused low-rank projection + hash/sign/insert -----------
// stage1: Ts[64][64] = X_tile[64x512] @ A_tile[512x64]  (k_vup idiom: plain
//         fp32 4x4 microtiles, As[64][32]/Bs[32][64], 32-d chunks)
// stage2: per covered head: out[64x64] = Ts_h[64x16] @ B_h[16x64] -> global
// stage3: per head: hash + signs read back from just-written global (L1-hot)
// grid (2048/64=32, 128/64=2, 2{q,k}) = 128 blocks, 256 thr
__global__ void k_proj(const float* __restrict__ Xq, const float* __restrict__ Xk,
                       const float* __restrict__ Aq, const float* __restrict__ Ak,
                       const float* __restrict__ Bq, const float* __restrict__ Bk,
                       const float* __restrict__ lsh) {
    int m0 = blockIdx.x * 64;
    int n0 = blockIdx.y * 64;
    int z = blockIdx.z;
    int tid = threadIdx.x;
    const float* X  = z ? Xk : Xq;
    const float* Am = z ? Ak : Aq;
    const float* Bm = z ? Bk : Bq;
    float* Out = z ? g_kup : g_qup;

    __shared__ float As[64][32];
    __shared__ float Bs[32][64];
    __shared__ float Ts[64][64];

    int tx = tid & 15, ty = tid >> 4;
    int b = m0 >> 10;
    int sbase = m0 & (SS - 1);
    int h0 = n0 >> 4;

    float c[4][4] = {};
    for (int d0 = 0; d0 < DD; d0 += 32) {
#pragma unroll
        for (int t = 0; t < 8; t++) {
            int i = tid + t * 256;
            int r = i >> 5, cc = i & 31;
            As[r][cc] = X[(m0 + r) * DD + d0 + cc];
        }
#pragma unroll
        for (int t = 0; t < 8; t++) {
            int i = tid + t * 256;
            int r = i >> 6, cc = i & 63;
            int gc = n0 + cc;
            int h = gc >> 4, rr = gc & 15;
            Bs[r][cc] = Am[h * (DD * RR) + (d0 + r) * RR + rr];
        }
        __syncthreads();
#pragma unroll 8
        for (int d = 0; d < 32; d++) {
            float a0 = As[ty*4+0][d], a1 = As[ty*4+1][d];
            float a2 = As[ty*4+2][d], a3 = As[ty*4+3][d];
            float4 bv = *(const float4*)&Bs[d][tx * 4];
            c[0][0] += a0*bv.x; c[0][1] += a0*bv.y; c[0][2] += a0*bv.z; c[0][3] += a0*bv.w;
            c[1][0] += a1*bv.x; c[1][1] += a1*bv.y; c[1][2] += a1*bv.z; c[1][3] += a1*bv.w;
            c[2][0] += a2*bv.x; c[2][1] += a2*bv.y; c[2][2] += a2*bv.z; c[2][3] += a2*bv.w;
            c[3][0] += a3*bv.x; c[3][1] += a3*bv.y; c[3][2] += a3*bv.z; c[3][3] += a3*bv.w;
        }
        __syncthreads();
    }
#pragma unroll
    for (int i = 0; i < 4; i++)
        *(float4*)&Ts[ty*4 + i][tx*4] = make_float4(c[i][0], c[i][1], c[i][2], c[i][3]);
    __syncthreads();

    // stage2+3 per head (Bs reused as 16x64 B_h tile)
#pragma unroll
    for (int hl = 0; hl < 4; hl++) {
        int h = h0 + hl;
#pragma unroll
        for (int t = 0; t < 4; t++) {
            int i = tid + t * 256;
            int kk = i >> 6, cc = i & 63;
            Bs[kk][cc] = Bm[h * RR * DKK + kk * DKK + cc];
        }
        __syncthreads();
        float c4[4][4] = {};
#pragma unroll
        for (int kk = 0; kk < 16; kk++) {
            float a0 = Ts[ty*4+0][hl*16+kk], a1 = Ts[ty*4+1][hl*16+kk];
            float a2 = Ts[ty*4+2][hl*16+kk], a3 = Ts[ty*4+3][hl*16+kk];
            float4 bv = *(const float4*)&Bs[kk][tx * 4];
            c4[0][0] += a0*bv.x; c4[0][1] += a0*bv.y; c4[0][2] += a0*bv.z; c4[0][3] += a0*bv.w;
            c4[1][0] += a1*bv.x; c4[1][1] += a1*bv.y; c4[1][2] += a1*bv.z; c4[1][3] += a1*bv.w;
            c4[2][0] += a2*bv.x; c4[2][1] += a2*bv.y; c4[2][2] += a2*bv.z; c4[2][3] += a2*bv.w;
            c4[3][0] += a3*bv.x; c4[3][1] += a3*bv.y; c4[3][2] += a3*bv.z; c4[3][3] += a3*bv.w;
        }
#pragma unroll
        for (int i = 0; i < 4; i++) {
            int r = ty * 4 + i;
            *(float4*)&Out[(((b * HH + h) * SS) + sbase + r) * DKK + tx * 4] =
                make_float4(c4[i][0], c4[i][1], c4[i][2], c4[i][3]);
        }
        __syncthreads();   // global writes visible block-wide before stage3 reads
        // stage3: 128 items = 2 groups x 64 rows; rows are L1-hot
        if (tid < 128) {
            int g = tid >> 6, r = tid & 63;
            int s = sbase + r;
            const float4* rowp = (const float4*)&Out[(((b*HH + h) * SS) + s) * DKK + g * GDD];
            const float4* pr = (const float4*)&lsh[(h * GG + g) * GDD * NHH];
            float a0 = 0.f, a1 = 0.f, a2 = 0.f, a3 = 0.f;
            unsigned sg = 0u;
#pragma unroll
            for (int dq = 0; dq < GDD / 4; dq++) {
                float4 vv = rowp[dq];
                float vs[4] = {vv.x, vv.y, vv.z, vv.w};
#pragma unroll
                for (int e = 0; e < 4; e++) {
                    float v = vs[e];
                    float4 p = pr[dq * 4 + e];
                    if (v > 0.f) sg |= (1u << (dq * 4 + e));
                    a0 += v * p.x; a1 += v * p.y; a2 += v * p.z; a3 += v * p.w;
                }
            }
            unsigned hw = ((unsigned)(((int)floorf(a0 * 0.25f)) & 63))
                        | ((unsigned)(((int)floorf(a1 * 0.25f)) & 63) << 8)
                        | ((unsigned)(((int)floorf(a2 * 0.25f)) & 63) << 16)
                        | ((unsigned)(((int)floorf(a3 * 0.25f)) & 63) << 24);
            int idx = ((b * HH + h) * GG + g) * SS + s;
            if (z == 0) {
                g_hq[idx] = hw;
                if (b == BB - 1) g_qsign[(h * GG + g) * SS + s] = sg;
            } else {
                g_hk[idx] = hw;
                if (b == BB - 1) {
                    ull entry = (((ull)sg) << 32) | 0x80000000u | (unsigned)s;
                    unsigned slot = (sg * 2654435761u) >> 21;
                    while (atomicCAS(&g_htab[h * GG + g][slot & (TSLOTS - 1)], 0ull, entry) != 0ull)
                        slot++;
                }
            }
        }
        __syncthreads();
    }
}

// ---------------- B: candidate generation (warp per row, lazy) --------------
__global__ void k_cand() {
    __shared__ unsigned unionw[4][32];
    __shared__ unsigned gmask[4][32];
    __shared__ int shcnt[4];
    int tid = threadIdx.x, wid = tid >> 5, lane = tid & 31;
    int row = blockIdx.x * 4 + wid;
    int s = row & (SS - 1), h = (row >> 10) & 7, b = row >> 13;
    unionw[wid][lane] = 0u;
    __syncwarp();
    for (int g = 0; g < GG; g++) {
        gmask[wid][lane] = 0u;
        __syncwarp();
        int hg = h * GG + g;
        unsigned qsig = g_qsign[hg * SS + s];
        unsigned hqv = g_hq[((b * HH + h) * GG + g) * SS + s];
        const ull* tab = g_htab[hg];
        const unsigned* hkp = &g_hk[((b * HH + h) * GG + g) * SS];
        unsigned start = (qsig * 2654435761u) >> 21;
        int gcnt = 0;
        for (int w = 0; w < TSLOTS / 32; w++) {
            int p = (start + w * 32 + lane) & (TSLOTS - 1);
            ull e = tab[p];
            bool empty = (e == 0ull);
            unsigned em = __ballot_sync(0xffffffffu, empty);
            unsigned valid = em ? ((em & (unsigned)(-(int)em)) - 1u) : 0xffffffffu;
            bool mt = false; int j = 0;
            if (!empty && ((valid >> lane) & 1u) && (unsigned)(e >> 32) == qsig) {
                j = (int)(e & 0x3FFu);
                mt = (__vcmpeq4(hqv, hkp[j]) != 0u);
            }
            unsigned bal = __ballot_sync(0xffffffffu, mt);
            if (mt) atomicOr(&gmask[wid][j >> 5], 1u << (j & 31));
            gcnt += __popc(bal);
            if (em) break;
        }
        if (gcnt > KMAX) {
            // rare fallback: compute scores for flagged j's, exact 64th-largest
            const float* qbase = &g_qup[row * DKK + g * GDD];
            const float* kbase = &g_kup[(b * HH + h) * SS * DKK + g * GDD];
            int* mix = &g_midx[(size_t)row * 1024];
            float* msf = &g_msc[(size_t)row * 1024];
            if (lane == 0) shcnt[wid] = 0;
            __syncwarp();
            unsigned w = gmask[wid][lane];
            while (w) {
                int bpos = __ffs(w) - 1;
                w &= w - 1;
                int j = lane * 32 + bpos;
                float a = 0.f;
                const float* kr = kbase + j * DKK;
#pragma unroll
                for (int d = 0; d < GDD; d++) a += qbase[d] * kr[d];
                int rk = atomicAdd(&shcnt[wid], 1);
                mix[rk] = j; msf[rk] = a;
            }
            __syncwarp();
            gmask[wid][lane] = 0u;
            __syncwarp();
            unsigned prefix = 0u; int kk = KMAX;
            for (int bit = 31; bit >= 0; bit--) {
                int local = 0;
                for (int i = lane; i < gcnt; i += 32) {
                    unsigned key = f2u_ord(msf[i]);
                    unsigned hi2 = (bit == 31) ? 0u : (key >> (bit + 1));
                    if (hi2 == prefix && ((key >> bit) & 1u)) local++;
                }
#pragma unroll
                for (int off = 16; off; off >>= 1) local += __shfl_xor_sync(0xffffffffu, local, off);
                if (local >= kk) prefix = (prefix << 1) | 1u;
                else { kk -= local; prefix <<= 1; }
            }
            for (int i = lane; i < gcnt; i += 32)
                if (f2u_ord(msf[i]) >= prefix)
                    atomicOr(&gmask[wid][mix[i] >> 5], 1u << (mix[i] & 31));
        }
        __syncwarp();
        unionw[wid][lane] |= gmask[wid][lane];
        __syncwarp();
    }
    unsigned w = unionw[wid][lane];
    int c = __popc(w);
    int pre = c;
#pragma unroll
    for (int off = 1; off < 32; off <<= 1) {
        int n = __shfl_up_sync(0xffffffffu, pre, off);
        if (lane >= off) pre += n;
    }
    int excl = pre - c;
    int total = __shfl_sync(0xffffffffu, pre, 31);
    if (lane == 0) g_ccount[row] = (total > KMAX) ? KMAX : total;
    if (total > 0) {
        int* crow = &g_cand[row * KMAX];
        int rank = excl;
        while (w && rank < KMAX) {
            int bpos = __ffs(w) - 1;
            w &= w - 1;
            crow[rank++] = lane * 32 + bpos;
        }
    }
}

// ---------------- C: epilogue (zero-fill fast path; full fallback) -----------
// grid (S/64, DD/64, B), 256 thr. Per block: check its 512 row counts;
// all-zero -> zero out tile. Else compute attn (vup on the fly) + out proj.
// Also clears g_htab for the next call.
__global__ void k_epi(const float* __restrict__ value, const float* __restrict__ Wv,
                      const float* __restrict__ Wo, float* __restrict__ out) {
    int stile = blockIdx.x, ntile = blockIdx.y, b = blockIdx.z;
    int sbase = stile * 64, n0 = ntile * 64;
    int tid = threadIdx.x;
    __shared__ int nzflag;
    if (tid == 0) nzflag = 0;
    __syncthreads();
    int any = 0;
#pragma unroll
    for (int t = 0; t < 2; t++) {
        int item = tid + t * 256;       // 512 = 8 heads x 64 rows
        int h = item >> 6, r = item & 63;
        if (g_ccount[(b * HH + h) * SS + sbase + r] > 0) any = 1;
    }
    if (any) atomicOr(&nzflag, 1);
    // clear htab for next call (nothing reads it after k_cand)
    {
        int lin = ((b * gridDim.y + ntile) * gridDim.x + stile) * 256 + tid;
        if (lin < HH * GG * TSLOTS) ((ull*)g_htab)[lin] = 0ull;
    }
    __syncthreads();
    if (!nzflag) {
        float4 z4 = make_float4(0.f, 0.f, 0.f, 0.f);
#pragma unroll
        for (int t = 0; t < 4; t++) {
            int lin = tid + t * 256;    // 1024 float4 = 64 rows x 16
            int r = lin >> 4, c4i = lin & 15;
            *(float4*)&out[(b * SS + sbase + r) * DD + n0 + c4i * 4] = z4;
        }
        return;
    }
    // ---------- fallback: full sparse attention + output projection ----------
    __shared__ float Oh[64][65];
    __shared__ float Ws[64][65];
    __shared__ float sl[8][KMAX];
    int lane = tid & 31, w = tid >> 5;
    int tx = tid & 15, ty = tid >> 4;
    float acc[4][4] = {};
    for (int h = 0; h < HH; h++) {
        for (int rr = 0; rr < 8; rr++) {
            int r = w * 8 + rr;
            int row = (b * HH + h) * SS + sbase + r;
            int cnt = g_ccount[row];
            float o0 = 0.f, o1 = 0.f;
            if (cnt > 0) {
                const int* crow = &g_cand[row * KMAX];
                const float* q = &g_qup[row * DKK];
                const float* kb2 = &g_kup[(b * HH + h) * SS * DKK];
                float mx = NEGF;
                for (int c = 0; c < cnt; c++) {
                    int j = crow[c];
                    const float* kr = kb2 + j * DKK;
                    float a = q[lane] * kr[lane] + q[lane + 32] * kr[lane + 32];
#pragma unroll
                    for (int off = 16; off; off >>= 1) a += __shfl_xor_sync(0xffffffffu, a, off);
                    a *= 0.125f;
                    if (lane == 0) sl[w][c] = a;
                    mx = fmaxf(mx, a);
                }
                __syncwarp();
                float sum = 0.f;
                for (int c = 0; c < cnt; c++) {
                    float e = expf(sl[w][c] - mx);
                    sum += e;
                }
                __syncwarp();
                float inv = (sum > 0.f) ? (1.f / sum) : 0.f;
                for (int c = 0; c < cnt; c++) {
                    int j = crow[c];
                    float p = expf(sl[w][c] - mx) * inv;
                    const float* vr = &value[(b * SS + j) * DD];
                    const float* wv = &Wv[h * DD * DKK];
                    float v0 = 0.f, v1 = 0.f;
                    for (int d = 0; d < DD; d++) {
                        float vv = vr[d];
                        v0 += vv * wv[d * DKK + lane];
                        v1 += vv * wv[d * DKK + lane + 32];
                    }
                    o0 += p * v0; o1 += p * v1;
                }
            }
            Oh[r][lane] = o0; Oh[r][lane + 32] = o1;
        }
        __syncthreads();
#pragma unroll
        for (int t = 0; t < 16; t++) {
            int lin = tid + t * 256;    // 4096 = 64x64
            int kk = lin >> 6, cc = lin & 63;
            Ws[kk][cc] = Wo[(h * DKK + kk) * DD + n0 + cc];
        }
        __syncthreads();
        for (int kk = 0; kk < DKK; kk++) {
            float a0 = Oh[ty*4+0][kk], a1 = Oh[ty*4+1][kk];
            float a2 = Oh[ty*4+2][kk], a3 = Oh[ty*4+3][kk];
            float b0 = Ws[kk][tx*4+0], b1 = Ws[kk][tx*4+1];
            float b2 = Ws[kk][tx*4+2], b3 = Ws[kk][tx*4+3];
            acc[0][0] += a0*b0; acc[0][1] += a0*b1; acc[0][2] += a0*b2; acc[0][3] += a0*b3;
            acc[1][0] += a1*b0; acc[1][1] += a1*b1; acc[1][2] += a1*b2; acc[1][3] += a1*b3;
            acc[2][0] += a2*b0; acc[2][1] += a2*b1; acc[2][2] += a2*b2; acc[2][3] += a2*b3;
            acc[3][0] += a3*b0; acc[3][1] += a3*b1; acc[3][2] += a3*b2; acc[3][3] += a3*b3;
        }
        __syncthreads();
    }
#pragma unroll
    for (int i = 0; i < 4; i++) {
        float4 v = make_float4(acc[i][0], acc[i][1], acc[i][2], acc[i][3]);
        *(float4*)&out[(b * SS + sbase + ty * 4 + i) * DD + n0 + tx * 4] = v;
    }
}

// ---------------- launch ----------------------------------------------------
extern "C" void kernel_launch(void* const* d_in, const int* in_sizes, int n_in,
                              void* d_out, int out_size) {
    const float* query = (const float*)d_in[0];
    const float* key   = (const float*)d_in[1];
    const float* value = (const float*)d_in[2];
    const float* Aq    = (const float*)d_in[3];
    const float* Bq    = (const float*)d_in[4];
    const float* Ak    = (const float*)d_in[5];
    const float* Bk    = (const float*)d_in[6];
    const float* Wv    = (const float*)d_in[7];
    const float* Wo    = (const float*)d_in[8];
    const float* lsh   = (const float*)d_in[9];
    float* out = (float*)d_out;

    k_proj<<<dim3(BB * SS / 64, (HH * RR) / 64, 2), 256>>>(query, key, Aq, Ak, Bq, Bk, lsh);
    k_cand<<<BB * HH * SS / 4, 128>>>();
    k_epi<<<dim3(SS / 64, DD / 64, BB), 256>>>(value, Wv, Wo, out);
}

// round 12
// speedup vs baseline: 1.0768x; 1.0446x over previous
#include <cuda_runtime.h>
#include <cuda_bf16.h>
#include <stdint.h>

#define BB 2
#define SS 1024
#define DD 512
#define HH 8
#define DKK 64
#define RR 16
#define GG 2
#define GDD 32
#define NHH 4
#define KMAX 64
#define NEGF (-1e30f)
#define TSLOTS 2048

typedef unsigned long long ull;

// ---------------- scratch (device globals; no allocation allowed) ----------
// g_htab empty marker is 0 (matches zero-init at module load); k_epi re-clears
// it at the end of every call so each replay starts empty.
__device__ float g_qup[BB*HH*SS*DKK];   // [b][h][s][k]
__device__ float g_kup[BB*HH*SS*DKK];
__device__ unsigned g_hq[BB*HH*GG*SS];  // packed 4 hash bytes
__device__ unsigned g_hk[BB*HH*GG*SS];
__device__ unsigned g_qsign[HH*GG*SS];  // q sign masks from batch B-1
__device__ ull g_htab[HH*GG][TSLOTS];   // (ksign<<32)|0x80000000|idx; 0=empty
__device__ int g_cand[BB*HH*SS*KMAX];
__device__ int g_ccount[BB*HH*SS];
// overflow buffers for the (astronomically rare) many-match fallback path
__device__ int   g_midx[(size_t)BB*HH*SS*1024];
__device__ float g_msc[(size_t)BB*HH*SS*1024];

__device__ __forceinline__ unsigned f2u_ord(float f) {
    unsigned u = __float_as_uint(f);
    return (u & 0x80000000u) ? ~u : (u | 0x80000000u);
}

// ---------------- A: fused low-rank projection + hash/sign/insert -----------
// stage1: Ts[64][64] = X_tile[64x512] @ A_tile[512x64], 32-d chunks.
//   At[d][row] (X transposed, pad 68) -> A operand is ONE LDS.128 of 4
//   consecutive rows, 2 distinct addrs/warp (broadcast). B: LDS.128 4 cols.
//   Global loads for chunk i+1 prefetched into regs during chunk i compute.
// stage2: per covered head: out[64x64] = Ts_h[64x16] @ B_h[16x64] -> global
// stage3: per head: hash + signs read back from just-written global (L1-hot)
// grid (2048/64=32, 128/64=2, 2{q,k}) = 128 blocks, 256 thr
__global__ void k_proj(const float* __restrict__ Xq, const float* __restrict__ Xk,
                       const float* __restrict__ Aq, const float* __restrict__ Ak,
                       const float* __restrict__ Bq, const float* __restrict__ Bk,
                       const float* __restrict__ lsh) {
    int m0 = blockIdx.x * 64;
    int n0 = blockIdx.y * 64;
    int z = blockIdx.z;
    int tid = threadIdx.x;
    const float* X  = z ? Xk : Xq;
    const float* Am = z ? Ak : Aq;
    const float* Bm = z ? Bk : Bq;
    float* Out = z ? g_kup : g_qup;

    __shared__ __align__(16) float At[32][68];   // X transposed: At[d][row]
    __shared__ __align__(16) float Bs[32][64];   // proj: Bs[d][col]
    __shared__ __align__(16) float Ts[64][64];

    int tx = tid & 15, ty = tid >> 4;
    int b = m0 >> 10;
    int sbase = m0 & (SS - 1);
    int h0 = n0 >> 4;

    // per-thread load indices (fixed across chunks)
    int xrow0 = tid >> 3, xdq0 = tid & 7;          // t=0
    int xrow1 = (tid + 256) >> 3, xdq1 = (tid + 256) & 7;  // t=1

    float4 xv0, xv1;
    float bval[8];
    // prefetch chunk 0
    xv0 = *(const float4*)&X[(m0 + xrow0) * DD + 0 + xdq0 * 4];
    xv1 = *(const float4*)&X[(m0 + xrow1) * DD + 0 + xdq1 * 4];
#pragma unroll
    for (int t = 0; t < 8; t++) {
        int lin = tid + t * 256;
        int r = lin >> 6, cc = lin & 63;
        int gc = n0 + cc;
        int h = gc >> 4, rr = gc & 15;
        bval[t] = Am[h * (DD * RR) + (0 + r) * RR + rr];
    }

    float c[4][4] = {};
    for (int ch = 0; ch < 16; ch++) {
        // store prefetched regs to smem
        At[xdq0*4+0][xrow0] = xv0.x; At[xdq0*4+1][xrow0] = xv0.y;
        At[xdq0*4+2][xrow0] = xv0.z; At[xdq0*4+3][xrow0] = xv0.w;
        At[xdq1*4+0][xrow1] = xv1.x; At[xdq1*4+1][xrow1] = xv1.y;
        At[xdq1*4+2][xrow1] = xv1.z; At[xdq1*4+3][xrow1] = xv1.w;
#pragma unroll
        for (int t = 0; t < 8; t++) {
            int lin = tid + t * 256;
            int r = lin >> 6, cc = lin & 63;
            Bs[r][cc] = bval[t];
        }
        __syncthreads();
        // prefetch next chunk during compute
        if (ch < 15) {
            int dn = (ch + 1) * 32;
            xv0 = *(const float4*)&X[(m0 + xrow0) * DD + dn + xdq0 * 4];
            xv1 = *(const float4*)&X[(m0 + xrow1) * DD + dn + xdq1 * 4];
#pragma unroll
            for (int t = 0; t < 8; t++) {
                int lin = tid + t * 256;
                int r = lin >> 6, cc = lin & 63;
                int gc = n0 + cc;
                int h = gc >> 4, rr = gc & 15;
                bval[t] = Am[h * (DD * RR) + (dn + r) * RR + rr];
            }
        }
#pragma unroll
        for (int d = 0; d < 32; d++) {
            float4 av = *(const float4*)&At[d][ty * 4];
            float4 bv = *(const float4*)&Bs[d][tx * 4];
            c[0][0] += av.x*bv.x; c[0][1] += av.x*bv.y; c[0][2] += av.x*bv.z; c[0][3] += av.x*bv.w;
            c[1][0] += av.y*bv.x; c[1][1] += av.y*bv.y; c[1][2] += av.y*bv.z; c[1][3] += av.y*bv.w;
            c[2][0] += av.z*bv.x; c[2][1] += av.z*bv.y; c[2][2] += av.z*bv.z; c[2][3] += av.z*bv.w;
            c[3][0] += av.w*bv.x; c[3][1] += av.w*bv.y; c[3][2] += av.w*bv.z; c[3][3] += av.w*bv.w;
        }
        __syncthreads();
    }
#pragma unroll
    for (int i = 0; i < 4; i++)
        *(float4*)&Ts[ty*4 + i][tx*4] = make_float4(c[i][0], c[i][1], c[i][2], c[i][3]);
    __syncthreads();

    // stage2+3 per head (Bs reused as 16x64 B_h tile)
#pragma unroll
    for (int hl = 0; hl < 4; hl++) {
        int h = h0 + hl;
#pragma unroll
        for (int t = 0; t < 4; t++) {
            int i = tid + t * 256;
            int kk = i >> 6, cc = i & 63;
            Bs[kk][cc] = Bm[h * RR * DKK + kk * DKK + cc];
        }
        __syncthreads();
        float c4[4][4] = {};
#pragma unroll
        for (int kk = 0; kk < 16; kk++) {
            float a0 = Ts[ty*4+0][hl*16+kk], a1 = Ts[ty*4+1][hl*16+kk];
            float a2 = Ts[ty*4+2][hl*16+kk], a3 = Ts[ty*4+3][hl*16+kk];
            float4 bv = *(const float4*)&Bs[kk][tx * 4];
            c4[0][0] += a0*bv.x; c4[0][1] += a0*bv.y; c4[0][2] += a0*bv.z; c4[0][3] += a0*bv.w;
            c4[1][0] += a1*bv.x; c4[1][1] += a1*bv.y; c4[1][2] += a1*bv.z; c4[1][3] += a1*bv.w;
            c4[2][0] += a2*bv.x; c4[2][1] += a2*bv.y; c4[2][2] += a2*bv.z; c4[2][3] += a2*bv.w;
            c4[3][0] += a3*bv.x; c4[3][1] += a3*bv.y; c4[3][2] += a3*bv.z; c4[3][3] += a3*bv.w;
        }
#pragma unroll
        for (int i = 0; i < 4; i++) {
            int r = ty * 4 + i;
            *(float4*)&Out[(((b * HH + h) * SS) + sbase + r) * DKK + tx * 4] =
                make_float4(c4[i][0], c4[i][1], c4[i][2], c4[i][3]);
        }
        __syncthreads();   // global writes visible block-wide before stage3 reads
        // stage3: 128 items = 2 groups x 64 rows; rows are L1-hot
        if (tid < 128) {
            int g = tid >> 6, r = tid & 63;
            int s = sbase + r;
            const float4* rowp = (const float4*)&Out[(((b*HH + h) * SS) + s) * DKK + g * GDD];
            const float4* pr = (const float4*)&lsh[(h * GG + g) * GDD * NHH];
            float a0 = 0.f, a1 = 0.f, a2 = 0.f, a3 = 0.f;
            unsigned sg = 0u;
#pragma unroll
            for (int dq = 0; dq < GDD / 4; dq++) {
                float4 vv = rowp[dq];
                float vs[4] = {vv.x, vv.y, vv.z, vv.w};
#pragma unroll
                for (int e = 0; e < 4; e++) {
                    float v = vs[e];
                    float4 p = pr[dq * 4 + e];
                    if (v > 0.f) sg |= (1u << (dq * 4 + e));
                    a0 += v * p.x; a1 += v * p.y; a2 += v * p.z; a3 += v * p.w;
                }
            }
            unsigned hw = ((unsigned)(((int)floorf(a0 * 0.25f)) & 63))
                        | ((unsigned)(((int)floorf(a1 * 0.25f)) & 63) << 8)
                        | ((unsigned)(((int)floorf(a2 * 0.25f)) & 63) << 16)
                        | ((unsigned)(((int)floorf(a3 * 0.25f)) & 63) << 24);
            int idx = ((b * HH + h) * GG + g) * SS + s;
            if (z == 0) {
                g_hq[idx] = hw;
                if (b == BB - 1) g_qsign[(h * GG + g) * SS + s] = sg;
            } else {
                g_hk[idx] = hw;
                if (b == BB - 1) {
                    ull entry = (((ull)sg) << 32) | 0x80000000u | (unsigned)s;
                    unsigned slot = (sg * 2654435761u) >> 21;
                    while (atomicCAS(&g_htab[h * GG + g][slot & (TSLOTS - 1)], 0ull, entry) != 0ull)
                        slot++;
                }
            }
        }
        __syncthreads();
    }
}

// ---------------- B: candidate generation (warp per row, lazy) --------------
__global__ void k_cand() {
    __shared__ unsigned unionw[4][32];
    __shared__ unsigned gmask[4][32];
    __shared__ int shcnt[4];
    int tid = threadIdx.x, wid = tid >> 5, lane = tid & 31;
    int row = blockIdx.x * 4 + wid;
    int s = row & (SS - 1), h = (row >> 10) & 7, b = row >> 13;
    unionw[wid][lane] = 0u;
    __syncwarp();
    for (int g = 0; g < GG; g++) {
        gmask[wid][lane] = 0u;
        __syncwarp();
        int hg = h * GG + g;
        unsigned qsig = g_qsign[hg * SS + s];
        unsigned hqv = g_hq[((b * HH + h) * GG + g) * SS + s];
        const ull* tab = g_htab[hg];
        const unsigned* hkp = &g_hk[((b * HH + h) * GG + g) * SS];
        unsigned start = (qsig * 2654435761u) >> 21;
        int gcnt = 0;
        for (int w = 0; w < TSLOTS / 32; w++) {
            int p = (start + w * 32 + lane) & (TSLOTS - 1);
            ull e = tab[p];
            bool empty = (e == 0ull);
            unsigned em = __ballot_sync(0xffffffffu, empty);
            unsigned valid = em ? ((em & (unsigned)(-(int)em)) - 1u) : 0xffffffffu;
            bool mt = false; int j = 0;
            if (!empty && ((valid >> lane) & 1u) && (unsigned)(e >> 32) == qsig) {
                j = (int)(e & 0x3FFu);
                mt = (__vcmpeq4(hqv, hkp[j]) != 0u);
            }
            unsigned bal = __ballot_sync(0xffffffffu, mt);
            if (mt) atomicOr(&gmask[wid][j >> 5], 1u << (j & 31));
            gcnt += __popc(bal);
            if (em) break;
        }
        if (gcnt > KMAX) {
            // rare fallback: compute scores for flagged j's, exact 64th-largest
            const float* qbase = &g_qup[row * DKK + g * GDD];
            const float* kbase = &g_kup[(b * HH + h) * SS * DKK + g * GDD];
            int* mix = &g_midx[(size_t)row * 1024];
            float* msf = &g_msc[(size_t)row * 1024];
            if (lane == 0) shcnt[wid] = 0;
            __syncwarp();
            unsigned w = gmask[wid][lane];
            while (w) {
                int bpos = __ffs(w) - 1;
                w &= w - 1;
                int j = lane * 32 + bpos;
                float a = 0.f;
                const float* kr = kbase + j * DKK;
#pragma unroll
                for (int d = 0; d < GDD; d++) a += qbase[d] * kr[d];
                int rk = atomicAdd(&shcnt[wid], 1);
                mix[rk] = j; msf[rk] = a;
            }
            __syncwarp();
            gmask[wid][lane] = 0u;
            __syncwarp();
            unsigned prefix = 0u; int kk = KMAX;
            for (int bit = 31; bit >= 0; bit--) {
                int local = 0;
                for (int i = lane; i < gcnt; i += 32) {
                    unsigned key = f2u_ord(msf[i]);
                    unsigned hi2 = (bit == 31) ? 0u : (key >> (bit + 1));
                    if (hi2 == prefix && ((key >> bit) & 1u)) local++;
                }
#pragma unroll
                for (int off = 16; off; off >>= 1) local += __shfl_xor_sync(0xffffffffu, local, off);
                if (local >= kk) prefix = (prefix << 1) | 1u;
                else { kk -= local; prefix <<= 1; }
            }
            for (int i = lane; i < gcnt; i += 32)
                if (f2u_ord(msf[i]) >= prefix)
                    atomicOr(&gmask[wid][mix[i] >> 5], 1u << (mix[i] & 31));
        }
        __syncwarp();
        unionw[wid][lane] |= gmask[wid][lane];
        __syncwarp();
    }
    unsigned w = unionw[wid][lane];
    int c = __popc(w);
    int pre = c;
#pragma unroll
    for (int off = 1; off < 32; off <<= 1) {
        int n = __shfl_up_sync(0xffffffffu, pre, off);
        if (lane >= off) pre += n;
    }
    int excl = pre - c;
    int total = __shfl_sync(0xffffffffu, pre, 31);
    if (lane == 0) g_ccount[row] = (total > KMAX) ? KMAX : total;
    if (total > 0) {
        int* crow = &g_cand[row * KMAX];
        int rank = excl;
        while (w && rank < KMAX) {
            int bpos = __ffs(w) - 1;
            w &= w - 1;
            crow[rank++] = lane * 32 + bpos;
        }
    }
}

// ---------------- C: epilogue (zero-fill fast path; full fallback) -----------
// grid (S/64, DD/64, B), 256 thr. Per block: check its 512 row counts;
// all-zero -> zero out tile. Else compute attn (vup on the fly) + out proj.
// Also clears g_htab for the next call.
__global__ void k_epi(const float* __restrict__ value, const float* __restrict__ Wv,
                      const float* __restrict__ Wo, float* __restrict__ out) {
    int stile = blockIdx.x, ntile = blockIdx.y, b = blockIdx.z;
    int sbase = stile * 64, n0 = ntile * 64;
    int tid = threadIdx.x;
    __shared__ int nzflag;
    if (tid == 0) nzflag = 0;
    __syncthreads();
    int any = 0;
#pragma unroll
    for (int t = 0; t < 2; t++) {
        int item = tid + t * 256;       // 512 = 8 heads x 64 rows
        int h = item >> 6, r = item & 63;
        if (g_ccount[(b * HH + h) * SS + sbase + r] > 0) any = 1;
    }
    if (any) atomicOr(&nzflag, 1);
    // clear htab for next call (nothing reads it after k_cand)
    {
        int lin = ((b * gridDim.y + ntile) * gridDim.x + stile) * 256 + tid;
        if (lin < HH * GG * TSLOTS) ((ull*)g_htab)[lin] = 0ull;
    }
    __syncthreads();
    if (!nzflag) {
        float4 z4 = make_float4(0.f, 0.f, 0.f, 0.f);
#pragma unroll
        for (int t = 0; t < 4; t++) {
            int lin = tid + t * 256;    // 1024 float4 = 64 rows x 16
            int r = lin >> 4, c4i = lin & 15;
            *(float4*)&out[(b * SS + sbase + r) * DD + n0 + c4i * 4] = z4;
        }
        return;
    }
    // ---------- fallback: full sparse attention + output projection ----------
    __shared__ float Oh[64][65];
    __shared__ float Ws[64][65];
    __shared__ float sl[8][KMAX];
    int lane = tid & 31, w = tid >> 5;
    int tx = tid & 15, ty = tid >> 4;
    float acc[4][4] = {};
    for (int h = 0; h < HH; h++) {
        for (int rr = 0; rr < 8; rr++) {
            int r = w * 8 + rr;
            int row = (b * HH + h) * SS + sbase + r;
            int cnt = g_ccount[row];
            float o0 = 0.f, o1 = 0.f;
            if (cnt > 0) {
                const int* crow = &g_cand[row * KMAX];
                const float* q = &g_qup[row * DKK];
                const float* kb2 = &g_kup[(b * HH + h) * SS * DKK];
                float mx = NEGF;
                for (int c = 0; c < cnt; c++) {
                    int j = crow[c];
                    const float* kr = kb2 + j * DKK;
                    float a = q[lane] * kr[lane] + q[lane + 32] * kr[lane + 32];
#pragma unroll
                    for (int off = 16; off; off >>= 1) a += __shfl_xor_sync(0xffffffffu, a, off);
                    a *= 0.125f;
                    if (lane == 0) sl[w][c] = a;
                    mx = fmaxf(mx, a);
                }
                __syncwarp();
                float sum = 0.f;
                for (int c = 0; c < cnt; c++) {
                    float e = expf(sl[w][c] - mx);
                    sum += e;
                }
                __syncwarp();
                float inv = (sum > 0.f) ? (1.f / sum) : 0.f;
                for (int c = 0; c < cnt; c++) {
                    int j = crow[c];
                    float p = expf(sl[w][c] - mx) * inv;
                    const float* vr = &value[(b * SS + j) * DD];
                    const float* wv = &Wv[h * DD * DKK];
                    float v0 = 0.f, v1 = 0.f;
                    for (int d = 0; d < DD; d++) {
                        float vv = vr[d];
                        v0 += vv * wv[d * DKK + lane];
                        v1 += vv * wv[d * DKK + lane + 32];
                    }
                    o0 += p * v0; o1 += p * v1;
                }
            }
            Oh[r][lane] = o0; Oh[r][lane + 32] = o1;
        }
        __syncthreads();
#pragma unroll
        for (int t = 0; t < 16; t++) {
            int lin = tid + t * 256;    // 4096 = 64x64
            int kk = lin >> 6, cc = lin & 63;
            Ws[kk][cc] = Wo[(h * DKK + kk) * DD + n0 + cc];
        }
        __syncthreads();
        for (int kk = 0; kk < DKK; kk++) {
            float a0 = Oh[ty*4+0][kk], a1 = Oh[ty*4+1][kk];
            float a2 = Oh[ty*4+2][kk], a3 = Oh[ty*4+3][kk];
            float b0 = Ws[kk][tx*4+0], b1 = Ws[kk][tx*4+1];
            float b2 = Ws[kk][tx*4+2], b3 = Ws[kk][tx*4+3];
            acc[0][0] += a0*b0; acc[0][1] += a0*b1; acc[0][2] += a0*b2; acc[0][3] += a0*b3;
            acc[1][0] += a1*b0; acc[1][1] += a1*b1; acc[1][2] += a1*b2; acc[1][3] += a1*b3;
            acc[2][0] += a2*b0; acc[2][1] += a2*b1; acc[2][2] += a2*b2; acc[2][3] += a2*b3;
            acc[3][0] += a3*b0; acc[3][1] += a3*b1; acc[3][2] += a3*b2; acc[3][3] += a3*b3;
        }
        __syncthreads();
    }
#pragma unroll
    for (int i = 0; i < 4; i++) {
        float4 v = make_float4(acc[i][0], acc[i][1], acc[i][2], acc[i][3]);
        *(float4*)&out[(b * SS + sbase + ty * 4 + i) * DD + n0 + tx * 4] = v;
    }
}

// ---------------- launch ----------------------------------------------------
extern "C" void kernel_launch(void* const* d_in, const int* in_sizes, int n_in,
                              void* d_out, int out_size) {
    const float* query = (const float*)d_in[0];
    const float* key   = (const float*)d_in[1];
    const float* value = (const float*)d_in[2];
    const float* Aq    = (const float*)d_in[3];
    const float* Bq    = (const float*)d_in[4];
    const float* Ak    = (const float*)d_in[5];
    const float* Bk    = (const float*)d_in[6];
    const float* Wv    = (const float*)d_in[7];
    const float* Wo    = (const float*)d_in[8];
    const float* lsh   = (const float*)d_in[9];
    float* out = (float*)d_out;

    k_proj<<<dim3(BB * SS / 64, (HH * RR) / 64, 2), 256>>>(query, key, Aq, Ak, Bq, Bk, lsh);
    k_cand<<<BB * HH * SS / 4, 128>>>();
    k_epi<<<dim3(SS / 64, DD / 64, BB), 256>>>(value, Wv, Wo, out);
}